// round 2
// baseline (speedup 1.0000x reference)
#include <cuda_runtime.h>
#include <cstdint>

// ============================================================================
// y[4096,4096] = x @ W^T + b (fp32), via generic-PTX mma.sync tf32 path.
// (tcgen05 PTX is sm_103a-arch-specific; harness compiles compute_103 generic
//  PTX, so legacy tensor path is the only tensor path available.)
//
// CTA tile 128x128, BK=32, 4-stage cp.async pipeline, 8 warps (64x32 each),
// mma.sync m16n8k8 tf32 with cvt.rna.tf32 on fragments (round-to-nearest,
// zero-mean error), fp32 accumulate, fused bias epilogue.
// ============================================================================

#define KDIM 4096
#define MT 128
#define NT 128
#define BK 32
#define STAGES 4
#define K_ITERS (KDIM / BK)            // 128
#define STAGE_BYTES (2 * MT * BK * 4)  // A(16KB) + B(16KB) = 32KB
#define A_OFF 0
#define B_OFF (MT * BK * 4)            // 16384
#define SMEM_TOTAL (STAGES * STAGE_BYTES)  // 131072

__device__ __forceinline__ uint32_t smem_u32(const void* p) {
    uint32_t a;
    asm("{ .reg .u64 t; cvta.to.shared.u64 t, %1; cvt.u32.u64 %0, t; }"
        : "=r"(a) : "l"(p));
    return a;
}

__device__ __forceinline__ void cp_async16(uint32_t dst, const void* src) {
    asm volatile("cp.async.cg.shared.global [%0], [%1], 16;"
                 :: "r"(dst), "l"(src) : "memory");
}
__device__ __forceinline__ void cp_commit() {
    asm volatile("cp.async.commit_group;" ::: "memory");
}
__device__ __forceinline__ void cp_wait2() {
    asm volatile("cp.async.wait_group 2;" ::: "memory");
}

__device__ __forceinline__ uint32_t lds_tf32(uint32_t addr) {
    float f;
    asm volatile("ld.shared.f32 %0, [%1];" : "=f"(f) : "r"(addr));
    uint32_t r;
    asm("cvt.rna.tf32.f32 %0, %1;" : "=r"(r) : "f"(f));
    return r;
}

__device__ __forceinline__ void mma_tf32(float* c, const uint32_t* a, const uint32_t* b) {
    asm volatile(
        "mma.sync.aligned.m16n8k8.row.col.f32.tf32.tf32.f32 "
        "{%0,%1,%2,%3}, {%4,%5,%6,%7}, {%8,%9}, {%0,%1,%2,%3};"
        : "+f"(c[0]), "+f"(c[1]), "+f"(c[2]), "+f"(c[3])
        : "r"(a[0]), "r"(a[1]), "r"(a[2]), "r"(a[3]), "r"(b[0]), "r"(b[1]));
}

// ---------------------------------------------------------------------------
__global__ void __launch_bounds__(256, 1) gemm_tf32_mma(
    const float* __restrict__ X,
    const float* __restrict__ W,
    const float* __restrict__ bias,
    float* __restrict__ out)
{
    extern __shared__ char smem[];
    const uint32_t sb = smem_u32(smem);

    const int tid  = threadIdx.x;
    const int lane = tid & 31;
    const int warp = tid >> 5;
    const int wm   = warp & 1;   // 2 warp-rows   (64 rows each)
    const int wn   = warp >> 1;  // 4 warp-cols   (32 cols each)

    const int mt0 = (blockIdx.x & 31) * MT;   // M tile (fast dim: B reuse in L2)
    const int nt0 = (blockIdx.x >> 5) * NT;   // N tile

    // ---- cp.async source/dest geometry (per thread, constant) ----
    // Each stage: A = 1024 x 16B chunks, B = 1024. Thread does 4 + 4 chunks.
    // chunk c = tid + i*256 -> row = tid/8 + 32*i, col4 = tid&7 (16B groups).
    const int crow  = tid >> 3;            // 0..31
    const int ccol4 = tid & 7;             // 0..7
    const uint32_t swc = (uint32_t)((ccol4 ^ (crow & 7)) << 4); // swizzled 16B slot
    const float* gA = X + (size_t)(mt0 + crow) * KDIM + ccol4 * 4;
    const float* gB = W + (size_t)(nt0 + crow) * KDIM + ccol4 * 4;
    const uint32_t sA = sb + A_OFF + crow * 128 + swc;
    const uint32_t sB = sb + B_OFF + crow * 128 + swc;

    // ---- fragment-load geometry ----
    const int fr  = lane >> 2;               // 0..7 (fragment row within 8)
    const int fb  = (lane & 3) * 4;          // byte offset within 16B group
    // swizzled 16B-group table: phys16[g] = (g ^ fr) * 16
    uint32_t swx[8];
    #pragma unroll
    for (int g = 0; g < 8; g++) swx[g] = (uint32_t)((g ^ fr) << 4);

    const uint32_t aBase = sb + A_OFF + (wm * 64 + fr) * 128 + fb;
    const uint32_t bBase = sb + B_OFF + (wn * 32 + fr) * 128 + fb;

    float acc[4][4][4];   // [mtile][ntile][reg]
    #pragma unroll
    for (int i = 0; i < 4; i++)
        #pragma unroll
        for (int j = 0; j < 4; j++)
            #pragma unroll
            for (int r = 0; r < 4; r++) acc[i][j][r] = 0.f;

    // ---- prologue: fill stages 0..2 ----
    #pragma unroll
    for (int s = 0; s < STAGES - 1; s++) {
        const uint32_t st = s * STAGE_BYTES;
        const int kc = s * BK;
        #pragma unroll
        for (int i = 0; i < 4; i++) {
            cp_async16(sA + st + i * 4096, gA + (size_t)i * 32 * KDIM + kc);
            cp_async16(sB + st + i * 4096, gB + (size_t)i * 32 * KDIM + kc);
        }
        cp_commit();
    }

    // ---- mainloop ----
    #pragma unroll 1
    for (int k = 0; k < K_ITERS; k++) {
        cp_wait2();
        __syncthreads();

        // refill stage (k+3)%4 (consumed at iter k-1; barrier above protects it)
        if (k + STAGES - 1 < K_ITERS) {
            const uint32_t st = ((k + STAGES - 1) & (STAGES - 1)) * STAGE_BYTES;
            const int kc = (k + STAGES - 1) * BK;
            #pragma unroll
            for (int i = 0; i < 4; i++) {
                cp_async16(sA + st + i * 4096, gA + (size_t)i * 32 * KDIM + kc);
                cp_async16(sB + st + i * 4096, gB + (size_t)i * 32 * KDIM + kc);
            }
        }
        cp_commit();   // one group per iteration (possibly empty) keeps count fixed

        const uint32_t st = (k & (STAGES - 1)) * STAGE_BYTES;

        #pragma unroll
        for (int ks = 0; ks < 4; ks++) {
            uint32_t afr[4][4];   // [mtile][reg]
            uint32_t bfr[4][2];   // [ntile][reg]
            #pragma unroll
            for (int mt = 0; mt < 4; mt++) {
                const uint32_t rb = aBase + st + mt * 2048;
                #pragma unroll
                for (int r = 0; r < 4; r++)
                    afr[mt][r] = lds_tf32(rb + (r & 1) * 1024 + swx[ks * 2 + (r >> 1)]);
            }
            #pragma unroll
            for (int nt = 0; nt < 4; nt++) {
                const uint32_t rb = bBase + st + nt * 1024;
                #pragma unroll
                for (int r = 0; r < 2; r++)
                    bfr[nt][r] = lds_tf32(rb + swx[ks * 2 + r]);
            }
            #pragma unroll
            for (int mt = 0; mt < 4; mt++)
                #pragma unroll
                for (int nt = 0; nt < 4; nt++)
                    mma_tf32(acc[mt][nt], afr[mt], bfr[nt]);
        }
    }

    // ---- epilogue: bias + store ----
    const int orow0 = mt0 + wm * 64 + fr;          // + mtile*16 (+8 for c2,c3)
    const int ocol0 = nt0 + wn * 32 + 2 * (lane & 3);

    #pragma unroll
    for (int mt = 0; mt < 4; mt++) {
        #pragma unroll
        for (int nt = 0; nt < 4; nt++) {
            const int col = ocol0 + nt * 8;
            const float2 bv = *reinterpret_cast<const float2*>(bias + col);
            const int r0 = orow0 + mt * 16;
            float2 v0 = { acc[mt][nt][0] + bv.x, acc[mt][nt][1] + bv.y };
            float2 v1 = { acc[mt][nt][2] + bv.x, acc[mt][nt][3] + bv.y };
            *reinterpret_cast<float2*>(out + (size_t)r0 * KDIM + col) = v0;
            *reinterpret_cast<float2*>(out + (size_t)(r0 + 8) * KDIM + col) = v1;
        }
    }
}

// ---------------------------------------------------------------------------
extern "C" void kernel_launch(void* const* d_in, const int* in_sizes, int n_in,
                              void* d_out, int out_size) {
    const float* x    = (const float*)d_in[0];
    const float* w    = (const float*)d_in[1];
    const float* bias = (const float*)d_in[2];
    float* out        = (float*)d_out;

    static bool attr_set = false;   // host-side attribute cache only (no device state)
    if (!attr_set) {
        cudaFuncSetAttribute(gemm_tf32_mma,
                             cudaFuncAttributeMaxDynamicSharedMemorySize, SMEM_TOTAL);
        attr_set = true;
    }

    // 32 M-tiles x 32 N-tiles = 1024 CTAs; M varies fastest (B-tile L2 reuse).
    gemm_tf32_mma<<<1024, 256, SMEM_TOTAL>>>(x, w, bias, out);
}

// round 3
// speedup vs baseline: 1.2263x; 1.2263x over previous
#include <cuda_runtime.h>
#include <cstdint>

// ============================================================================
// y = x @ W^T + b  (4096^3, fp32) via mma.sync.m16n8k8.tf32 (generic PTX path;
// tcgen05 PTX rejected by the compute_103 virtual target).
//
// Round-3 design:
//  * One-time pre-pass converts x,W to tf32 (cvt.rna) AND permutes them into
//    exact mma-fragment order in __device__ scratch:
//      A'[m128][k32][mt8][ks4][lane32][4 floats]  (thread's 4 A-regs = 16B)
//      B'[n128][k32][nt16][ks4][lane32][2 floats] (thread's 2 B-regs = 8B)
//    -> mainloop has ZERO cvt, cp.async is a pure linear copy (no swizzle),
//       fragment loads are LDS.128 / LDS.64 (conflict-free).
//  * GEMM: CTA tile 128x128, 4 warps (warp tile 64x64), BK=32, 3-stage
//    cp.async pipeline, 2 CTAs/SM, fused bias epilogue.
// ============================================================================

#define KDIM 4096
#define BK 32
#define STAGES 3
#define K_ITERS (KDIM / BK)               // 128
#define A_STAGE 16384                     // 128 rows x 32 k x 4B
#define B_STAGE 16384
#define STAGE_BYTES (A_STAGE + B_STAGE)   // 32768
#define SMEM_TOTAL (STAGES * STAGE_BYTES) // 98304

__device__ float g_xa[(size_t)KDIM * KDIM];   // A' fragment-ordered tf32
__device__ float g_wb[(size_t)KDIM * KDIM];   // B' fragment-ordered tf32

// ---------------------------------------------------------------------------
__device__ __forceinline__ uint32_t smem_u32(const void* p) {
    uint32_t a;
    asm("{ .reg .u64 t; cvta.to.shared.u64 t, %1; cvt.u32.u64 %0, t; }"
        : "=r"(a) : "l"(p));
    return a;
}
__device__ __forceinline__ void cp_async16(uint32_t dst, const void* src) {
    asm volatile("cp.async.cg.shared.global [%0], [%1], 16;"
                 :: "r"(dst), "l"(src) : "memory");
}
__device__ __forceinline__ void cp_commit() {
    asm volatile("cp.async.commit_group;" ::: "memory");
}
__device__ __forceinline__ void cp_wait1() {
    asm volatile("cp.async.wait_group 1;" ::: "memory");
}
__device__ __forceinline__ uint32_t cvt_tf32(float f) {
    uint32_t r;
    asm("cvt.rna.tf32.f32 %0, %1;" : "=r"(r) : "f"(f));
    return r;
}
__device__ __forceinline__ void lds128(uint32_t* r, uint32_t a) {
    asm volatile("ld.shared.v4.b32 {%0,%1,%2,%3}, [%4];"
                 : "=r"(r[0]), "=r"(r[1]), "=r"(r[2]), "=r"(r[3]) : "r"(a));
}
__device__ __forceinline__ void lds64(uint32_t* r, uint32_t a) {
    asm volatile("ld.shared.v2.b32 {%0,%1}, [%2];"
                 : "=r"(r[0]), "=r"(r[1]) : "r"(a));
}
__device__ __forceinline__ void mma_tf32(float* c, const uint32_t* a, const uint32_t* b) {
    asm volatile(
        "mma.sync.aligned.m16n8k8.row.col.f32.tf32.tf32.f32 "
        "{%0,%1,%2,%3}, {%4,%5,%6,%7}, {%8,%9}, {%0,%1,%2,%3};"
        : "+f"(c[0]), "+f"(c[1]), "+f"(c[2]), "+f"(c[3])
        : "r"(a[0]), "r"(a[1]), "r"(a[2]), "r"(a[3]), "r"(b[0]), "r"(b[1]));
}

// ---------------------------------------------------------------------------
// Pre-pass A: gather 4 fragment values per 16B chunk, cvt.rna, coalesced store.
// chunk idx: [m128:5][k32:7][mt:3][ks:2][lane:5]
// a0=(row,col) a1=(row+8,col) a2=(row,col+4) a3=(row+8,col+4)
// ---------------------------------------------------------------------------
__global__ void __launch_bounds__(256) prep_a(const float* __restrict__ src,
                                              uint4* __restrict__ dst) {
    const int idx = blockIdx.x * 256 + threadIdx.x;        // 4,194,304 chunks
    const int lane = idx & 31;
    const int ks   = (idx >> 5) & 3;
    const int mt   = (idx >> 7) & 7;
    const int k32  = (idx >> 10) & 127;
    const int m128 = idx >> 17;
    const int row = m128 * 128 + mt * 16 + (lane >> 2);
    const int col = k32 * 32 + ks * 8 + (lane & 3);
    const float* p = src + (size_t)row * KDIM + col;
    uint4 o;
    o.x = cvt_tf32(__ldg(p));
    o.y = cvt_tf32(__ldg(p + (size_t)8 * KDIM));
    o.z = cvt_tf32(__ldg(p + 4));
    o.w = cvt_tf32(__ldg(p + (size_t)8 * KDIM + 4));
    dst[idx] = o;
}

// Pre-pass B: 8B units. idx: [n128:5][k32:7][nt:4][ks:2][lane:5]
// b0=(n,k) b1=(n,k+4)
__global__ void __launch_bounds__(256) prep_b(const float* __restrict__ src,
                                              uint2* __restrict__ dst) {
    const int idx = blockIdx.x * 256 + threadIdx.x;        // 8,388,608 units
    const int lane = idx & 31;
    const int ks   = (idx >> 5) & 3;
    const int nt   = (idx >> 7) & 15;
    const int k32  = (idx >> 11) & 127;
    const int n128 = idx >> 18;
    const int n = n128 * 128 + nt * 8 + (lane >> 2);
    const int k = k32 * 32 + ks * 8 + (lane & 3);
    const float* p = src + (size_t)n * KDIM + k;
    uint2 o;
    o.x = cvt_tf32(__ldg(p));
    o.y = cvt_tf32(__ldg(p + 4));
    dst[idx] = o;
}

// ---------------------------------------------------------------------------
// GEMM: 128 threads (4 warps, 2x2 of 64x64 warp tiles), 2 CTAs/SM.
// ---------------------------------------------------------------------------
__global__ void __launch_bounds__(128, 2) gemm_tf32_mma(
    const float* __restrict__ Ap,
    const float* __restrict__ Bp,
    const float* __restrict__ bias,
    float* __restrict__ out)
{
    extern __shared__ char smem[];
    const uint32_t sb = smem_u32(smem);

    const int tid  = threadIdx.x;
    const int lane = tid & 31;
    const int warp = tid >> 5;
    const int wm   = warp & 1;     // 2 warp rows (64 each)
    const int wn   = warp >> 1;    // 2 warp cols (64 each)

    const int m128 = blockIdx.x & 31;   // M fastest (B-tile L2 reuse)
    const int n128 = blockIdx.x >> 5;

    // Linear stage sources: one (m128,k32) block = 16KB contiguous.
    const char* gA = (const char*)Ap + (size_t)m128 * 128 * 16384;
    const char* gB = (const char*)Bp + (size_t)n128 * 128 * 16384;

    // Fragment bases (stage offset added in loop).
    const uint32_t aFragBase = sb + (uint32_t)(wm * 4) * 2048 + lane * 16;
    const uint32_t bFragBase = sb + A_STAGE + (uint32_t)(wn * 8) * 1024 + lane * 8;

    float acc[4][8][4];
    #pragma unroll
    for (int i = 0; i < 4; i++)
        #pragma unroll
        for (int j = 0; j < 8; j++)
            #pragma unroll
            for (int r = 0; r < 4; r++) acc[i][j][r] = 0.f;

    // ---- prologue: stages 0,1 ----
    #pragma unroll
    for (int s = 0; s < STAGES - 1; s++) {
        const uint32_t d = sb + s * STAGE_BYTES + tid * 16;
        const char* srcA = gA + (size_t)s * 16384 + tid * 16;
        const char* srcB = gB + (size_t)s * 16384 + tid * 16;
        #pragma unroll
        for (int i = 0; i < 8; i++) {
            cp_async16(d + i * 2048, srcA + i * 2048);
            cp_async16(d + A_STAGE + i * 2048, srcB + i * 2048);
        }
        cp_commit();
    }

    // ---- mainloop ----
    #pragma unroll 1
    for (int k = 0; k < K_ITERS; k++) {
        cp_wait1();
        __syncthreads();

        if (k + STAGES - 1 < K_ITERS) {
            const int kf = k + STAGES - 1;
            const uint32_t d = sb + (kf % STAGES) * STAGE_BYTES + tid * 16;
            const char* srcA = gA + (size_t)kf * 16384 + tid * 16;
            const char* srcB = gB + (size_t)kf * 16384 + tid * 16;
            #pragma unroll
            for (int i = 0; i < 8; i++) {
                cp_async16(d + i * 2048, srcA + i * 2048);
                cp_async16(d + A_STAGE + i * 2048, srcB + i * 2048);
            }
        }
        cp_commit();

        const uint32_t st = (uint32_t)(k % STAGES) * STAGE_BYTES;
        const uint32_t ab = aFragBase + st;
        const uint32_t bb = bFragBase + st;

        #pragma unroll
        for (int ks = 0; ks < 4; ks++) {
            uint32_t afr[4][4];
            uint32_t bfr[8][2];
            #pragma unroll
            for (int mt = 0; mt < 4; mt++)
                lds128(afr[mt], ab + mt * 2048 + ks * 512);
            #pragma unroll
            for (int nt = 0; nt < 8; nt++)
                lds64(bfr[nt], bb + nt * 1024 + ks * 256);
            #pragma unroll
            for (int mt = 0; mt < 4; mt++)
                #pragma unroll
                for (int nt = 0; nt < 8; nt++)
                    mma_tf32(acc[mt][nt], afr[mt], bfr[nt]);
        }
    }

    // ---- epilogue: bias + float2 stores ----
    const int fr = lane >> 2;
    const int orow0 = m128 * 128 + wm * 64 + fr;
    const int ocol0 = n128 * 128 + wn * 64 + 2 * (lane & 3);

    #pragma unroll
    for (int mt = 0; mt < 4; mt++) {
        #pragma unroll
        for (int nt = 0; nt < 8; nt++) {
            const int col = ocol0 + nt * 8;
            const float2 bv = *reinterpret_cast<const float2*>(bias + col);
            const int r0 = orow0 + mt * 16;
            float2 v0 = { acc[mt][nt][0] + bv.x, acc[mt][nt][1] + bv.y };
            float2 v1 = { acc[mt][nt][2] + bv.x, acc[mt][nt][3] + bv.y };
            *reinterpret_cast<float2*>(out + (size_t)r0 * KDIM + col) = v0;
            *reinterpret_cast<float2*>(out + (size_t)(r0 + 8) * KDIM + col) = v1;
        }
    }
}

// ---------------------------------------------------------------------------
extern "C" void kernel_launch(void* const* d_in, const int* in_sizes, int n_in,
                              void* d_out, int out_size) {
    const float* x    = (const float*)d_in[0];
    const float* w    = (const float*)d_in[1];
    const float* bias = (const float*)d_in[2];
    float* out        = (float*)d_out;

    void* gx = nullptr;
    void* gw = nullptr;
    cudaGetSymbolAddress(&gx, g_xa);
    cudaGetSymbolAddress(&gw, g_wb);

    static bool attr_set = false;  // host-side only
    if (!attr_set) {
        cudaFuncSetAttribute(gemm_tf32_mma,
                             cudaFuncAttributeMaxDynamicSharedMemorySize, SMEM_TOTAL);
        attr_set = true;
    }

    // Fragment-order + tf32 round-to-nearest pre-passes.
    prep_a<<<16384, 256>>>(x, (uint4*)gx);
    prep_b<<<32768, 256>>>(w, (uint2*)gw);

    // 32 x 32 tiles of 128x128 = 1024 CTAs.
    gemm_tf32_mma<<<1024, 128, SMEM_TOTAL>>>((const float*)gx, (const float*)gw,
                                             bias, out);
}

// round 4
// speedup vs baseline: 2.4059x; 1.9619x over previous
#include <cuda_runtime.h>
#include <cuda_fp16.h>
#include <cstdint>

// ============================================================================
// y = x @ W^T + b (4096^3 fp32) via mma.sync.m16n8k16.f32.f16.f16.f32.
// fp16 mantissa (10 bit) == tf32 mantissa, fp32 accumulate -> same ~3e-4
// rel err as the tf32 path, at 2x tensor rate and half the memory traffic.
//
// Pre-pass: cvt fp32 -> fp16 (RN) AND permute into exact mma fragment order:
//   A'[m128][kb128][mt16:8][ks:2][lane:32][4xb32]   (16B per thread-frag)
//   B'[n128][kb128][nt8:16][ks:2][lane:32][2xb32]   (8B per thread-frag)
// Mainloop: pure linear cp.async, LDS.128/LDS.64 fragment loads, zero cvt.
// GEMM: CTA 128x128, 4 warps (64x64 each), BK=32, 4-stage pipeline, 2 CTA/SM.
// ============================================================================

#define KDIM 4096
#define BK 32
#define STAGES 4
#define K_ITERS (KDIM / BK)               // 128
#define A_STAGE 8192                      // 128 x 32 x 2B
#define B_STAGE 8192
#define STAGE_BYTES (A_STAGE + B_STAGE)   // 16384
#define SMEM_TOTAL (STAGES * STAGE_BYTES) // 65536

__device__ __half g_xa[(size_t)KDIM * KDIM];   // A' fragment-ordered fp16
__device__ __half g_wb[(size_t)KDIM * KDIM];   // B' fragment-ordered fp16

// ---------------------------------------------------------------------------
__device__ __forceinline__ uint32_t smem_u32(const void* p) {
    uint32_t a;
    asm("{ .reg .u64 t; cvta.to.shared.u64 t, %1; cvt.u32.u64 %0, t; }"
        : "=r"(a) : "l"(p));
    return a;
}
__device__ __forceinline__ void cp_async16(uint32_t dst, const void* src) {
    asm volatile("cp.async.cg.shared.global [%0], [%1], 16;"
                 :: "r"(dst), "l"(src) : "memory");
}
__device__ __forceinline__ void cp_commit() {
    asm volatile("cp.async.commit_group;" ::: "memory");
}
__device__ __forceinline__ void cp_wait2() {
    asm volatile("cp.async.wait_group 2;" ::: "memory");
}
__device__ __forceinline__ void lds128(uint32_t* r, uint32_t a) {
    asm volatile("ld.shared.v4.b32 {%0,%1,%2,%3}, [%4];"
                 : "=r"(r[0]), "=r"(r[1]), "=r"(r[2]), "=r"(r[3]) : "r"(a));
}
__device__ __forceinline__ void lds64(uint32_t* r, uint32_t a) {
    asm volatile("ld.shared.v2.b32 {%0,%1}, [%2];"
                 : "=r"(r[0]), "=r"(r[1]) : "r"(a));
}
__device__ __forceinline__ void mma_f16(float* c, const uint32_t* a, const uint32_t* b) {
    asm volatile(
        "mma.sync.aligned.m16n8k16.row.col.f32.f16.f16.f32 "
        "{%0,%1,%2,%3}, {%4,%5,%6,%7}, {%8,%9}, {%0,%1,%2,%3};"
        : "+f"(c[0]), "+f"(c[1]), "+f"(c[2]), "+f"(c[3])
        : "r"(a[0]), "r"(a[1]), "r"(a[2]), "r"(a[3]), "r"(b[0]), "r"(b[1]));
}
__device__ __forceinline__ uint32_t pack_h2(float lo, float hi) {
    __half2 h = __floats2half2_rn(lo, hi);   // .x = lo (low 16 bits)
    return *reinterpret_cast<uint32_t*>(&h);
}

// ---------------------------------------------------------------------------
// Pre-pass A: each thread emits one 16B fragment (4 b32 = 8 halves).
// idx bits: [m128:5][kb:7][mt16:3][ks:1][lane:5]  -> 2,097,152 threads
// a0={(r,k),(r,k+1)} a1={(r+8,k),..} a2={(r,k+8),..} a3={(r+8,k+8),..}
// ---------------------------------------------------------------------------
__global__ void __launch_bounds__(256) prep_a(const float* __restrict__ src,
                                              uint4* __restrict__ dst) {
    const int idx  = blockIdx.x * 256 + threadIdx.x;
    const int lane = idx & 31;
    const int ks   = (idx >> 5) & 1;
    const int mt16 = (idx >> 6) & 7;
    const int kb   = (idx >> 9) & 127;
    const int m128 = idx >> 16;
    const int row = m128 * 128 + mt16 * 16 + (lane >> 2);
    const int col = kb * 32 + ks * 16 + (lane & 3) * 2;
    const float* p = src + (size_t)row * KDIM + col;
    const float2 v00 = *reinterpret_cast<const float2*>(p);
    const float2 v10 = *reinterpret_cast<const float2*>(p + (size_t)8 * KDIM);
    const float2 v01 = *reinterpret_cast<const float2*>(p + 8);
    const float2 v11 = *reinterpret_cast<const float2*>(p + (size_t)8 * KDIM + 8);
    uint4 o;
    o.x = pack_h2(v00.x, v00.y);
    o.y = pack_h2(v10.x, v10.y);
    o.z = pack_h2(v01.x, v01.y);
    o.w = pack_h2(v11.x, v11.y);
    dst[idx] = o;
}

// Pre-pass B: each thread emits one 8B fragment (2 b32 = 4 halves).
// idx bits: [n128:5][kb:7][nt8:4][ks:1][lane:5] -> 4,194,304 threads
// b0={W[n][k],W[n][k+1]}  b1={W[n][k+8],W[n][k+9]}   (B[k][n] = W[n][k])
__global__ void __launch_bounds__(256) prep_b(const float* __restrict__ src,
                                              uint2* __restrict__ dst) {
    const int idx  = blockIdx.x * 256 + threadIdx.x;
    const int lane = idx & 31;
    const int ks   = (idx >> 5) & 1;
    const int nt8  = (idx >> 6) & 15;
    const int kb   = (idx >> 10) & 127;
    const int n128 = idx >> 17;
    const int n = n128 * 128 + nt8 * 8 + (lane >> 2);
    const int k = kb * 32 + ks * 16 + (lane & 3) * 2;
    const float* p = src + (size_t)n * KDIM + k;
    const float2 v0 = *reinterpret_cast<const float2*>(p);
    const float2 v1 = *reinterpret_cast<const float2*>(p + 8);
    uint2 o;
    o.x = pack_h2(v0.x, v0.y);
    o.y = pack_h2(v1.x, v1.y);
    dst[idx] = o;
}

// ---------------------------------------------------------------------------
// GEMM: 128 threads (2x2 warps of 64x64), 2 CTAs/SM.
// ---------------------------------------------------------------------------
__global__ void __launch_bounds__(128, 2) gemm_f16_mma(
    const __half* __restrict__ Ap,
    const __half* __restrict__ Bp,
    const float* __restrict__ bias,
    float* __restrict__ out)
{
    extern __shared__ char smem[];
    const uint32_t sb = smem_u32(smem);

    const int tid  = threadIdx.x;
    const int lane = tid & 31;
    const int warp = tid >> 5;
    const int wm   = warp & 1;
    const int wn   = warp >> 1;

    const int m128 = blockIdx.x & 31;   // M fastest (B-tile L2 reuse)
    const int n128 = blockIdx.x >> 5;

    // Linear stage sources: one (tile,kb) block = 8KB contiguous.
    const char* gA = (const char*)Ap + (size_t)m128 * 128 * 8192;
    const char* gB = (const char*)Bp + (size_t)n128 * 128 * 8192;

    // Fragment bases within a stage.
    const uint32_t aFragBase = sb + (uint32_t)wm * 4096 + lane * 16;
    const uint32_t bFragBase = sb + A_STAGE + (uint32_t)wn * 4096 + lane * 8;

    float acc[4][8][4];
    #pragma unroll
    for (int i = 0; i < 4; i++)
        #pragma unroll
        for (int j = 0; j < 8; j++)
            #pragma unroll
            for (int r = 0; r < 4; r++) acc[i][j][r] = 0.f;

    // ---- prologue: fill stages 0..2 (4 A + 4 B chunks of 16B per thread) ----
    #pragma unroll
    for (int s = 0; s < STAGES - 1; s++) {
        const uint32_t d = sb + s * STAGE_BYTES + tid * 16;
        const char* srcA = gA + (size_t)s * 8192 + tid * 16;
        const char* srcB = gB + (size_t)s * 8192 + tid * 16;
        #pragma unroll
        for (int i = 0; i < 4; i++) {
            cp_async16(d + i * 2048, srcA + i * 2048);
            cp_async16(d + A_STAGE + i * 2048, srcB + i * 2048);
        }
        cp_commit();
    }

    // ---- mainloop ----
    #pragma unroll 1
    for (int k = 0; k < K_ITERS; k++) {
        cp_wait2();
        __syncthreads();

        if (k + STAGES - 1 < K_ITERS) {
            const int kf = k + STAGES - 1;
            const uint32_t d = sb + (kf & (STAGES - 1)) * STAGE_BYTES + tid * 16;
            const char* srcA = gA + (size_t)kf * 8192 + tid * 16;
            const char* srcB = gB + (size_t)kf * 8192 + tid * 16;
            #pragma unroll
            for (int i = 0; i < 4; i++) {
                cp_async16(d + i * 2048, srcA + i * 2048);
                cp_async16(d + A_STAGE + i * 2048, srcB + i * 2048);
            }
        }
        cp_commit();

        const uint32_t st = (uint32_t)(k & (STAGES - 1)) * STAGE_BYTES;
        const uint32_t ab = aFragBase + st;
        const uint32_t bb = bFragBase + st;

        #pragma unroll
        for (int ks = 0; ks < 2; ks++) {
            uint32_t afr[4][4];
            uint32_t bfr[8][2];
            #pragma unroll
            for (int mt = 0; mt < 4; mt++)
                lds128(afr[mt], ab + mt * 1024 + ks * 512);
            #pragma unroll
            for (int nt = 0; nt < 8; nt++)
                lds64(bfr[nt], bb + nt * 512 + ks * 256);
            #pragma unroll
            for (int mt = 0; mt < 4; mt++)
                #pragma unroll
                for (int nt = 0; nt < 8; nt++)
                    mma_f16(acc[mt][nt], afr[mt], bfr[nt]);
        }
    }

    // ---- epilogue: bias + float2 stores ----
    const int fr = lane >> 2;
    const int orow0 = m128 * 128 + wm * 64 + fr;
    const int ocol0 = n128 * 128 + wn * 64 + 2 * (lane & 3);

    #pragma unroll
    for (int mt = 0; mt < 4; mt++) {
        #pragma unroll
        for (int nt = 0; nt < 8; nt++) {
            const int col = ocol0 + nt * 8;
            const float2 bv = *reinterpret_cast<const float2*>(bias + col);
            const int r0 = orow0 + mt * 16;
            float2 v0 = { acc[mt][nt][0] + bv.x, acc[mt][nt][1] + bv.y };
            float2 v1 = { acc[mt][nt][2] + bv.x, acc[mt][nt][3] + bv.y };
            *reinterpret_cast<float2*>(out + (size_t)r0 * KDIM + col) = v0;
            *reinterpret_cast<float2*>(out + (size_t)(r0 + 8) * KDIM + col) = v1;
        }
    }
}

// ---------------------------------------------------------------------------
extern "C" void kernel_launch(void* const* d_in, const int* in_sizes, int n_in,
                              void* d_out, int out_size) {
    const float* x    = (const float*)d_in[0];
    const float* w    = (const float*)d_in[1];
    const float* bias = (const float*)d_in[2];
    float* out        = (float*)d_out;

    void* gx = nullptr;
    void* gw = nullptr;
    cudaGetSymbolAddress(&gx, g_xa);
    cudaGetSymbolAddress(&gw, g_wb);

    static bool attr_set = false;  // host-side only
    if (!attr_set) {
        cudaFuncSetAttribute(gemm_f16_mma,
                             cudaFuncAttributeMaxDynamicSharedMemorySize, SMEM_TOTAL);
        attr_set = true;
    }

    prep_a<<<8192, 256>>>(x, (uint4*)gx);
    prep_b<<<16384, 256>>>(w, (uint2*)gw);

    gemm_f16_mma<<<1024, 128, SMEM_TOTAL>>>((const __half*)gx, (const __half*)gw,
                                            bias, out);
}